// round 2
// baseline (speedup 1.0000x reference)
#include <cuda_runtime.h>

#define BB 4096
#define TT 2048
#define II 4
#define HH 3

typedef unsigned long long u64;

__device__ __forceinline__ float tanh_ap(float x) {
    float y; asm("tanh.approx.f32 %0, %1;" : "=f"(y) : "f"(x)); return y;
}
__device__ __forceinline__ u64 fma2(u64 a, u64 b, u64 c) {
    u64 d; asm("fma.rn.f32x2 %0, %1, %2, %3;" : "=l"(d) : "l"(a), "l"(b), "l"(c)); return d;
}
__device__ __forceinline__ u64 pk2(float lo, float hi) {
    u64 d; asm("mov.b64 %0, {%1, %2};" : "=l"(d) : "f"(lo), "f"(hi)); return d;
}
__device__ __forceinline__ float hsum2(u64 v) {
    float lo, hi; asm("mov.b64 {%0, %1}, %2;" : "=f"(lo), "=f"(hi) : "l"(v)); return lo + hi;
}

// 4 lanes per sequence-pair group. Lane sub=0,1,2 own hidden unit sub
// (lane 3 duplicates unit 2 to keep the group converged for shfl).
// Each group processes TWO sequences (2G, 2G+1) interleaved for ILP.
// sigmoid(z) = 0.5*tanh(0.5 z)+0.5 with sigmoid-row weights pre-scaled by 0.5.
// Input+recurrent projections use packed f32x2 FMAs; x is read as double2 so
// (x0,x1),(x2,x3) pairs come pre-packed from the load.
__global__ void __launch_bounds__(128)
lstm_seq_kernel(const float* __restrict__ x,
                const float* __restrict__ Wih,
                const float* __restrict__ Whh,
                const float* __restrict__ bih,
                const float* __restrict__ bhh,
                const int*   __restrict__ lenw,
                float* __restrict__ out)
{
    const int lane = threadIdx.x & 31;
    const int sub  = threadIdx.x & 3;
    const int G    = (blockIdx.x * 128 + threadIdx.x) >> 2;  // group id 0..2047
    const int bA   = 2 * G;
    const int bB   = 2 * G + 1;
    const int base = lane & ~3;
    const unsigned gmask = 0xFu << base;

    const int unit = (sub < 3) ? sub : 2;

    // length dtype sniff (lengths >=1, so int32 elem 1 == 0 => int64 high word)
    const bool is64 = (lenw[1] == 0);
    int lenA = is64 ? lenw[2 * bA] : lenw[bA];
    int lenB = is64 ? lenw[2 * bB] : lenw[bB];
    lenA = min(max(lenA, 0), TT);
    lenB = min(max(lenB, 0), TT);
    const int lenMax = max(lenA, lenB);

    const int ri = unit, rf = 3 + unit, rg = 6 + unit, ro = 9 + unit;

    // gate scales: sigmoid rows (i,f,o) 0.5; tanh row (g) 1.0
    const float SI = 0.5f, SG = 1.0f;

    // packed input weights: (w0,w1) and (w2,w3) per gate
    u64 wxi01 = pk2(SI * Wih[ri*II+0], SI * Wih[ri*II+1]);
    u64 wxi23 = pk2(SI * Wih[ri*II+2], SI * Wih[ri*II+3]);
    u64 wxf01 = pk2(SI * Wih[rf*II+0], SI * Wih[rf*II+1]);
    u64 wxf23 = pk2(SI * Wih[rf*II+2], SI * Wih[rf*II+3]);
    u64 wxg01 = pk2(SG * Wih[rg*II+0], SG * Wih[rg*II+1]);
    u64 wxg23 = pk2(SG * Wih[rg*II+2], SG * Wih[rg*II+3]);
    u64 wxo01 = pk2(SI * Wih[ro*II+0], SI * Wih[ro*II+1]);
    u64 wxo23 = pk2(SI * Wih[ro*II+2], SI * Wih[ro*II+3]);

    // packed recurrent weights (wh0, wh1) + scalar wh2
    u64 whi01 = pk2(SI * Whh[ri*HH+0], SI * Whh[ri*HH+1]);
    u64 whf01 = pk2(SI * Whh[rf*HH+0], SI * Whh[rf*HH+1]);
    u64 whg01 = pk2(SG * Whh[rg*HH+0], SG * Whh[rg*HH+1]);
    u64 who01 = pk2(SI * Whh[ro*HH+0], SI * Whh[ro*HH+1]);
    const float whi2 = SI * Whh[ri*HH+2];
    const float whf2 = SI * Whh[rf*HH+2];
    const float whg2 = SG * Whh[rg*HH+2];
    const float who2 = SI * Whh[ro*HH+2];

    // packed biases: (bias, 0)
    u64 bi2 = pk2(SI * (bih[ri] + bhh[ri]), 0.0f);
    u64 bf2 = pk2(SI * (bih[rf] + bhh[rf]), 0.0f);
    u64 bg2 = pk2(SG * (bih[rg] + bhh[rg]), 0.0f);
    u64 bo2 = pk2(SI * (bih[ro] + bhh[ro]), 0.0f);

    float hA0 = 0.f, hA1 = 0.f, hA2 = 0.f, cA = 0.f;
    float hB0 = 0.f, hB1 = 0.f, hB2 = 0.f, cB = 0.f;

    const double2* __restrict__ xrA = (const double2*)(x + (size_t)bA * TT * II);
    const double2* __restrict__ xrB = (const double2*)(x + (size_t)bB * TT * II);
    float* __restrict__ orowA = out + (size_t)bA * TT * HH;
    float* __restrict__ orowB = out + (size_t)bB * TT * HH;

    // 8-deep register prefetch ring per sequence
    double2 bufA[8], bufB[8];
    #pragma unroll
    for (int p = 0; p < 8; p++) { bufA[p] = xrA[p]; bufB[p] = xrB[p]; }

    auto STEP = [&](double2 xv,
                    float& h0, float& h1, float& h2, float& c,
                    float* __restrict__ orow, int t, int len) {
        const u64 x01 = __double_as_longlong(xv.x);
        const u64 x23 = __double_as_longlong(xv.y);

        // input projection (independent of recurrence)
        u64 ai2 = fma2(x01, wxi01, bi2); ai2 = fma2(x23, wxi23, ai2);
        u64 af2 = fma2(x01, wxf01, bf2); af2 = fma2(x23, wxf23, af2);
        u64 ag2 = fma2(x01, wxg01, bg2); ag2 = fma2(x23, wxg23, ag2);
        u64 ao2 = fma2(x01, wxo01, bo2); ao2 = fma2(x23, wxo23, ao2);

        // recurrent projection (critical path starts here)
        const u64 ph = pk2(h0, h1);
        ai2 = fma2(ph, whi01, ai2);
        af2 = fma2(ph, whf01, af2);
        ag2 = fma2(ph, whg01, ag2);
        ao2 = fma2(ph, who01, ao2);

        float zi = fmaf(h2, whi2, hsum2(ai2));
        float zf = fmaf(h2, whf2, hsum2(af2));
        float zg = fmaf(h2, whg2, hsum2(ag2));
        float zo = fmaf(h2, who2, hsum2(ao2));

        const float ti = tanh_ap(zi);
        const float tf = tanh_ap(zf);
        const float tg = tanh_ap(zg);
        const float to_ = tanh_ap(zo);
        const float si = fmaf(ti, 0.5f, 0.5f);
        const float sf = fmaf(tf, 0.5f, 0.5f);
        const float so = fmaf(to_, 0.5f, 0.5f);

        c = fmaf(sf, c, si * tg);
        const float hn = so * tanh_ap(c);

        h0 = __shfl_sync(gmask, hn, base + 0);
        h1 = __shfl_sync(gmask, hn, base + 1);
        h2 = __shfl_sync(gmask, hn, base + 2);

        if (sub < 3 && t < len) orow[t * HH + sub] = hn;
    };

    int t = 0;
    const int nfull = lenMax & ~7;
    for (; t < nfull; t += 8) {
        #pragma unroll
        for (int u = 0; u < 8; u++) {
            double2 xa = bufA[u], xb = bufB[u];
            const int nt = t + 8 + u;
            if (nt < TT) { bufA[u] = xrA[nt]; bufB[u] = xrB[nt]; }
            STEP(xa, hA0, hA1, hA2, cA, orowA, t + u, lenA);
            STEP(xb, hB0, hB1, hB2, cB, orowB, t + u, lenB);
        }
    }
    {
        const int rem = lenMax - nfull;  // 0..7, uniform within the 4-lane group
        #pragma unroll
        for (int u = 0; u < 8; u++) {
            if (u < rem) {
                STEP(bufA[u], hA0, hA1, hA2, cA, orowA, nfull + u, lenA);
                STEP(bufB[u], hB0, hB1, hB2, cB, orowB, nfull + u, lenB);
            }
        }
    }

    // zero the masked tails (d_out is poisoned)
    for (int i = lenA * HH + sub; i < TT * HH; i += 4) orowA[i] = 0.0f;
    for (int i = lenB * HH + sub; i < TT * HH; i += 4) orowB[i] = 0.0f;
}

extern "C" void kernel_launch(void* const* d_in, const int* in_sizes, int n_in,
                              void* d_out, int out_size)
{
    const float* x   = (const float*)d_in[0];
    const float* Wih = (const float*)d_in[1];
    const float* Whh = (const float*)d_in[2];
    const float* bih = (const float*)d_in[3];
    const float* bhh = (const float*)d_in[4];
    const int*   len = (const int*)  d_in[5];
    float* out = (float*)d_out;
    (void)in_sizes; (void)n_in; (void)out_size;

    // 4096 seqs, 2 per 4-lane group -> 8192 threads = 64 blocks x 128
    lstm_seq_kernel<<<64, 128>>>(x, Wih, Whh, bih, bhh, len, out);
}

// round 3
// speedup vs baseline: 1.1730x; 1.1730x over previous
#include <cuda_runtime.h>

#define BB 4096
#define TT 2048
#define II 4
#define HH 3

typedef unsigned long long u64;

__device__ __forceinline__ float tanh_ap(float x) {
    float y; asm("tanh.approx.f32 %0, %1;" : "=f"(y) : "f"(x)); return y;
}
__device__ __forceinline__ u64 fma2(u64 a, u64 b, u64 c) {
    u64 d; asm("fma.rn.f32x2 %0, %1, %2, %3;" : "=l"(d) : "l"(a), "l"(b), "l"(c)); return d;
}
__device__ __forceinline__ u64 pk2(float lo, float hi) {
    u64 d; asm("mov.b64 %0, {%1, %2};" : "=l"(d) : "f"(lo), "f"(hi)); return d;
}
__device__ __forceinline__ void up2(u64 v, float& lo, float& hi) {
    asm("mov.b64 {%0, %1}, %2;" : "=f"(lo), "=f"(hi) : "l"(v));
}

// One THREAD per sequence: all 3 hidden units, all 12 gates in-thread.
// No shfl -> recurrence chain ~60 cyc; bundle bound by per-SMSP pipe
// throughput (15 MUFU, ~42 fma2). 128 single-warp blocks -> 1 warp/SMSP.
// Gates packed pairwise into f32x2: (i0,i1)(f0,f1)(g0,g1)(o0,o1)(i2,f2)(g2,o2).
// Sigmoid rows pre-scaled by 0.5 (sigmoid = 0.5*tanh(0.5z)+0.5).
// Main loop has NO length predication: runs ceil(len/4) chunks, stores
// 3xSTG.128 per chunk; zero_tail kernel afterwards zeroes all t >= len
// (also wiping any chunk-overrun garbage).
__global__ void __launch_bounds__(32, 1)
lstm_main(const float* __restrict__ x,
          const float* __restrict__ Wih,
          const float* __restrict__ Whh,
          const float* __restrict__ bih,
          const float* __restrict__ bhh,
          const int*   __restrict__ lenw,
          float* __restrict__ out)
{
    const int b = blockIdx.x * 32 + threadIdx.x;   // 128 blocks x 32 = 4096

    // length dtype sniff (lengths >= 1, so int32 elem 1 == 0 => int64 words)
    const bool is64 = (lenw[1] == 0);
    int len = is64 ? lenw[2 * b] : lenw[b];
    len = min(max(len, 1), TT);

    // row p of each pair, with per-row activation pre-scale
    const int r0s[6] = {0, 3, 6, 9, 2, 8};
    const int r1s[6] = {1, 4, 7, 10, 5, 11};

    u64 wx[6][II], wh[6][HH], bz[6];
    #pragma unroll
    for (int p = 0; p < 6; p++) {
        const int r0 = r0s[p], r1 = r1s[p];
        const float s0 = (r0 >= 6 && r0 <= 8) ? 1.0f : 0.5f;  // g rows raw
        const float s1 = (r1 >= 6 && r1 <= 8) ? 1.0f : 0.5f;
        #pragma unroll
        for (int k = 0; k < II; k++)
            wx[p][k] = pk2(s0 * Wih[r0 * II + k], s1 * Wih[r1 * II + k]);
        #pragma unroll
        for (int k = 0; k < HH; k++)
            wh[p][k] = pk2(s0 * Whh[r0 * HH + k], s1 * Whh[r1 * HH + k]);
        bz[p] = pk2(s0 * (bih[r0] + bhh[r0]), s1 * (bih[r1] + bhh[r1]));
    }

    float h0 = 0.f, h1 = 0.f, h2 = 0.f;
    float c0 = 0.f, c1 = 0.f, c2 = 0.f;

    const float4* __restrict__ xr = (const float4*)(x + (size_t)b * TT * II);
    float4* __restrict__ ov = (float4*)(out + (size_t)b * TT * HH);

    // prefetch ring, depth 4
    float4 buf[4];
    #pragma unroll
    for (int p = 0; p < 4; p++) buf[p] = __ldg(&xr[p]);

    const int trip = (len + 3) >> 2;
    for (int tc = 0; tc < trip; tc++) {
        float och[12];
        #pragma unroll
        for (int u = 0; u < 4; u++) {
            const float4 xv = buf[u];
            const int nt = 4 * tc + 4 + u;
            buf[u] = __ldg(&xr[min(nt, TT - 1)]);

            // input projection (independent of recurrence)
            const u64 xx0 = pk2(xv.x, xv.x), xx1 = pk2(xv.y, xv.y);
            const u64 xx2 = pk2(xv.z, xv.z), xx3 = pk2(xv.w, xv.w);
            u64 z[6];
            #pragma unroll
            for (int p = 0; p < 6; p++) {
                u64 a = fma2(xx0, wx[p][0], bz[p]);
                a = fma2(xx1, wx[p][1], a);
                a = fma2(xx2, wx[p][2], a);
                z[p] = fma2(xx3, wx[p][3], a);
            }
            // recurrent projection (critical path)
            const u64 hh0 = pk2(h0, h0), hh1 = pk2(h1, h1), hh2 = pk2(h2, h2);
            #pragma unroll
            for (int p = 0; p < 6; p++) {
                u64 a = fma2(hh0, wh[p][0], z[p]);
                a = fma2(hh1, wh[p][1], a);
                z[p] = fma2(hh2, wh[p][2], a);
            }

            float zi0, zi1, zf0, zf1, zg0, zg1, zo0, zo1, zi2, zf2, zg2, zo2;
            up2(z[0], zi0, zi1); up2(z[1], zf0, zf1); up2(z[2], zg0, zg1);
            up2(z[3], zo0, zo1); up2(z[4], zi2, zf2); up2(z[5], zg2, zo2);

            const float si0 = fmaf(tanh_ap(zi0), 0.5f, 0.5f);
            const float si1 = fmaf(tanh_ap(zi1), 0.5f, 0.5f);
            const float si2 = fmaf(tanh_ap(zi2), 0.5f, 0.5f);
            const float sf0 = fmaf(tanh_ap(zf0), 0.5f, 0.5f);
            const float sf1 = fmaf(tanh_ap(zf1), 0.5f, 0.5f);
            const float sf2 = fmaf(tanh_ap(zf2), 0.5f, 0.5f);
            const float tg0 = tanh_ap(zg0);
            const float tg1 = tanh_ap(zg1);
            const float tg2 = tanh_ap(zg2);
            const float so0 = fmaf(tanh_ap(zo0), 0.5f, 0.5f);
            const float so1 = fmaf(tanh_ap(zo1), 0.5f, 0.5f);
            const float so2 = fmaf(tanh_ap(zo2), 0.5f, 0.5f);

            c0 = fmaf(sf0, c0, si0 * tg0);
            c1 = fmaf(sf1, c1, si1 * tg1);
            c2 = fmaf(sf2, c2, si2 * tg2);

            h0 = so0 * tanh_ap(c0);
            h1 = so1 * tanh_ap(c1);
            h2 = so2 * tanh_ap(c2);

            och[3 * u + 0] = h0;
            och[3 * u + 1] = h1;
            och[3 * u + 2] = h2;
        }
        // 12 floats = 3 x STG.128; base 48B-aligned within 16B-aligned row
        ov[3 * tc + 0] = make_float4(och[0], och[1], och[2],  och[3]);
        ov[3 * tc + 1] = make_float4(och[4], och[5], och[6],  och[7]);
        ov[3 * tc + 2] = make_float4(och[8], och[9], och[10], och[11]);
    }
}

// Zero all positions t >= length[b] (reference masks them to 0; also wipes
// the main kernel's last-chunk overrun garbage). d_out is poisoned, so this
// must cover the whole masked region.
__global__ void zero_tail(const int* __restrict__ lenw, float* __restrict__ out)
{
    const int i = blockIdx.x * blockDim.x + threadIdx.x;   // over BB*TT
    if (i >= BB * TT) return;
    const int b = i >> 11;        // / TT
    const int t = i & (TT - 1);   // % TT
    const bool is64 = (lenw[1] == 0);
    const int len = is64 ? lenw[2 * b] : lenw[b];
    if (t >= len) {
        float* o = out + (size_t)i * HH;
        o[0] = 0.0f; o[1] = 0.0f; o[2] = 0.0f;
    }
}

extern "C" void kernel_launch(void* const* d_in, const int* in_sizes, int n_in,
                              void* d_out, int out_size)
{
    const float* x   = (const float*)d_in[0];
    const float* Wih = (const float*)d_in[1];
    const float* Whh = (const float*)d_in[2];
    const float* bih = (const float*)d_in[3];
    const float* bhh = (const float*)d_in[4];
    const int*   len = (const int*)  d_in[5];
    float* out = (float*)d_out;
    (void)in_sizes; (void)n_in; (void)out_size;

    // 4096 sequences, 1 thread each: 128 single-warp blocks -> 1 warp/SMSP
    lstm_main<<<128, 32>>>(x, Wih, Whh, bih, bhh, len, out);
    zero_tail<<<(BB * TT + 255) / 256, 256>>>(len, out);
}

// round 5
// speedup vs baseline: 1.4171x; 1.2081x over previous
#include <cuda_runtime.h>

#define BB 4096
#define TT 2048
#define II 4
#define HH 3

typedef unsigned long long u64;

__device__ __forceinline__ float tanh_ap(float x) {
    float y; asm("tanh.approx.f32 %0, %1;" : "=f"(y) : "f"(x)); return y;
}
__device__ __forceinline__ u64 fma2(u64 a, u64 b, u64 c) {
    u64 d; asm("fma.rn.f32x2 %0, %1, %2, %3;" : "=l"(d) : "l"(a), "l"(b), "l"(c)); return d;
}
__device__ __forceinline__ u64 pk2(float lo, float hi) {
    u64 d; asm("mov.b64 %0, {%1, %2};" : "=l"(d) : "f"(lo), "f"(hi)); return d;
}
__device__ __forceinline__ void up2(u64 v, float& lo, float& hi) {
    asm("mov.b64 {%0, %1}, %2;" : "=f"(lo), "=f"(hi) : "l"(v));
}

// One THREAD per sequence, but only 4 ACTIVE LANES per warp: 4096 seqs ->
// 1024 single-warp blocks -> ~7 blocks/SM -> ~1.7 warps per SMSP, so
// co-resident warps hide each other's MUFU/FMA latency (R3 had 1 warp/SMSP
// and ran fully latency-exposed at ~385 cyc/step).
// Per-warp instruction stream is identical regardless of active-lane count.
// Gates packed pairwise into f32x2: (i0,i1)(f0,f1)(g0,g1)(o0,o1)(i2,f2)(g2,o2);
// sigmoid rows pre-scaled by 0.5 (sigmoid = 0.5*tanh(0.5z)+0.5).
// Main loop is unpredicated (ceil(len/4) chunks, 3xSTG.128 each); the owner
// lane zeroes its chunk overrun, then all 32 lanes cooperatively zero the
// poisoned tails of the warp's 4 rows.
__global__ void __launch_bounds__(32)
lstm_main(const float* __restrict__ x,
          const float* __restrict__ Wih,
          const float* __restrict__ Whh,
          const float* __restrict__ bih,
          const float* __restrict__ bhh,
          const int*   __restrict__ lenw,
          float* __restrict__ out)
{
    const int lane = threadIdx.x;
    const int b = blockIdx.x * 4 + (lane & 3);   // 1024 blocks x 4 = 4096

    // length dtype sniff (lengths >= 1, so int32 elem 1 == 0 => int64 words)
    const bool is64 = (lenw[1] == 0);
    int len = is64 ? lenw[2 * b] : lenw[b];
    len = min(max(len, 1), TT);
    const int trip = (len + 3) >> 2;

    if (lane < 4) {
        // row pairs, with per-row activation pre-scale (g rows raw)
        const int r0s[6] = {0, 3, 6, 9, 2, 8};
        const int r1s[6] = {1, 4, 7, 10, 5, 11};

        u64 wx[6][II], wh[6][HH], bz[6];
        #pragma unroll
        for (int p = 0; p < 6; p++) {
            const int r0 = r0s[p], r1 = r1s[p];
            const float s0 = (r0 >= 6 && r0 <= 8) ? 1.0f : 0.5f;
            const float s1 = (r1 >= 6 && r1 <= 8) ? 1.0f : 0.5f;
            #pragma unroll
            for (int k = 0; k < II; k++)
                wx[p][k] = pk2(s0 * Wih[r0 * II + k], s1 * Wih[r1 * II + k]);
            #pragma unroll
            for (int k = 0; k < HH; k++)
                wh[p][k] = pk2(s0 * Whh[r0 * HH + k], s1 * Whh[r1 * HH + k]);
            bz[p] = pk2(s0 * (bih[r0] + bhh[r0]), s1 * (bih[r1] + bhh[r1]));
        }

        float h0 = 0.f, h1 = 0.f, h2 = 0.f;
        float c0 = 0.f, c1 = 0.f, c2 = 0.f;

        const float4* __restrict__ xr = (const float4*)(x + (size_t)b * TT * II);
        float4* __restrict__ ov = (float4*)(out + (size_t)b * TT * HH);

        // prefetch ring, depth 4 (distance ~4 steps * ~250cyc >> DRAM 577)
        float4 buf[4];
        #pragma unroll
        for (int p = 0; p < 4; p++) buf[p] = __ldg(&xr[p]);

        for (int tc = 0; tc < trip; tc++) {
            float och[12];
            #pragma unroll
            for (int u = 0; u < 4; u++) {
                const float4 xv = buf[u];
                const int nt = 4 * tc + 4 + u;
                buf[u] = __ldg(&xr[min(nt, TT - 1)]);

                // input projection (independent of recurrence)
                const u64 xx0 = pk2(xv.x, xv.x), xx1 = pk2(xv.y, xv.y);
                const u64 xx2 = pk2(xv.z, xv.z), xx3 = pk2(xv.w, xv.w);
                u64 z[6];
                #pragma unroll
                for (int p = 0; p < 6; p++) {
                    u64 a = fma2(xx0, wx[p][0], bz[p]);
                    a = fma2(xx1, wx[p][1], a);
                    a = fma2(xx2, wx[p][2], a);
                    z[p] = fma2(xx3, wx[p][3], a);
                }
                // recurrent projection (critical path)
                const u64 hh0 = pk2(h0, h0), hh1 = pk2(h1, h1), hh2 = pk2(h2, h2);
                #pragma unroll
                for (int p = 0; p < 6; p++) {
                    u64 a = fma2(hh0, wh[p][0], z[p]);
                    a = fma2(hh1, wh[p][1], a);
                    z[p] = fma2(hh2, wh[p][2], a);
                }

                float zi0, zi1, zf0, zf1, zg0, zg1, zo0, zo1, zi2, zf2, zg2, zo2;
                up2(z[0], zi0, zi1); up2(z[1], zf0, zf1); up2(z[2], zg0, zg1);
                up2(z[3], zo0, zo1); up2(z[4], zi2, zf2); up2(z[5], zg2, zo2);

                const float si0 = fmaf(tanh_ap(zi0), 0.5f, 0.5f);
                const float si1 = fmaf(tanh_ap(zi1), 0.5f, 0.5f);
                const float si2 = fmaf(tanh_ap(zi2), 0.5f, 0.5f);
                const float sf0 = fmaf(tanh_ap(zf0), 0.5f, 0.5f);
                const float sf1 = fmaf(tanh_ap(zf1), 0.5f, 0.5f);
                const float sf2 = fmaf(tanh_ap(zf2), 0.5f, 0.5f);
                const float tg0 = tanh_ap(zg0);
                const float tg1 = tanh_ap(zg1);
                const float tg2 = tanh_ap(zg2);
                const float so0 = fmaf(tanh_ap(zo0), 0.5f, 0.5f);
                const float so1 = fmaf(tanh_ap(zo1), 0.5f, 0.5f);
                const float so2 = fmaf(tanh_ap(zo2), 0.5f, 0.5f);

                c0 = fmaf(sf0, c0, si0 * tg0);
                c1 = fmaf(sf1, c1, si1 * tg1);
                c2 = fmaf(sf2, c2, si2 * tg2);

                h0 = so0 * tanh_ap(c0);
                h1 = so1 * tanh_ap(c1);
                h2 = so2 * tanh_ap(c2);

                och[3 * u + 0] = h0;
                och[3 * u + 1] = h1;
                och[3 * u + 2] = h2;
            }
            ov[3 * tc + 0] = make_float4(och[0], och[1], och[2],  och[3]);
            ov[3 * tc + 1] = make_float4(och[4], och[5], och[6],  och[7]);
            ov[3 * tc + 2] = make_float4(och[8], och[9], och[10], och[11]);
        }

        // owner zeroes its own chunk overrun [len*3, trip*12) (same thread ->
        // ordered after the loop's stores; <= 9 floats)
        float* __restrict__ orow = out + (size_t)b * TT * HH;
        for (int i = len * HH; i < trip * 12; i++) orow[i] = 0.0f;
    }
    __syncwarp();

    // cooperative zero of the poisoned tails: float4s [trip_s*3, 1536) per seq.
    // (every lane computed trip for seq (lane&3), so shfl from lane s works)
    #pragma unroll
    for (int s = 0; s < 4; s++) {
        const int bs = blockIdx.x * 4 + s;
        const int start4 = __shfl_sync(0xffffffffu, trip, s) * 3;
        float4* __restrict__ ovs = (float4*)(out + (size_t)bs * TT * HH);
        for (int i = start4 + lane; i < (TT * HH) / 4; i += 32)
            ovs[i] = make_float4(0.f, 0.f, 0.f, 0.f);
    }
}

extern "C" void kernel_launch(void* const* d_in, const int* in_sizes, int n_in,
                              void* d_out, int out_size)
{
    const float* x   = (const float*)d_in[0];
    const float* Wih = (const float*)d_in[1];
    const float* Whh = (const float*)d_in[2];
    const float* bih = (const float*)d_in[3];
    const float* bhh = (const float*)d_in[4];
    const int*   len = (const int*)  d_in[5];
    float* out = (float*)d_out;
    (void)in_sizes; (void)n_in; (void)out_size;

    // 4096 seqs, 4 per single-warp block -> 1024 warps -> ~1.7 warps/SMSP
    lstm_main<<<1024, 32>>>(x, Wih, Whh, bih, bhh, len, out);
}